// round 2
// baseline (speedup 1.0000x reference)
#include <cuda_runtime.h>
#include <math.h>

#define NN 100000
#define EE 1600000
#define INF 128
#define HID 256
#define GCO 256
#define FO  256

// Scratch (device globals: allocation-free)
__device__ __align__(16) float g_nfeats[(size_t)NN * HID];
__device__ __align__(16) float g_xw[(size_t)NN * GCO];
__device__ __align__(16) float g_gc[(size_t)NN * GCO];
__device__ int   g_count[NN];
__device__ int   g_cursor[NN];
__device__ int   g_offsets[NN + 1];
__device__ float g_dinv[NN];
__device__ int   g_csr[EE];
__device__ int   g_is64;   // 1 if edges/batch are int64, 0 if int32

// ---------------------------------------------------------------------------
// Detect int32 vs int64 edge buffer: int64 indices < 2^32 have zero odd words.
__global__ void detect_kernel(const unsigned int* __restrict__ ew, int nPairs) {
    __shared__ int nz;
    if (threadIdx.x == 0) nz = 0;
    __syncthreads();
    for (int i = threadIdx.x; i < nPairs; i += blockDim.x) {
        if (ew[2 * i + 1] != 0u) { nz = 1; break; }
    }
    __syncthreads();
    if (threadIdx.x == 0) g_is64 = (nz == 0) ? 1 : 0;
}

__device__ __forceinline__ long long ld_idx(const void* p, size_t i) {
    if (g_is64) return ((const long long*)p)[i];
    return (long long)((const int*)p)[i];
}

// ---------------------------------------------------------------------------
__global__ void zero_kernel(int n) {
    for (int i = blockIdx.x * blockDim.x + threadIdx.x; i < n;
         i += gridDim.x * blockDim.x) {
        g_count[i] = 0;
        g_cursor[i] = 0;
    }
}

__global__ void hist_kernel(const void* __restrict__ edges, int E) {
    for (int i = blockIdx.x * blockDim.x + threadIdx.x; i < E;
         i += gridDim.x * blockDim.x) {
        int d = (int)ld_idx(edges, (size_t)E + i);
        if (d >= 0 && d < NN) atomicAdd(&g_count[d], 1);
    }
}

__global__ void scan_kernel(int n) {
    __shared__ int sums[1024];
    int tid = threadIdx.x;
    int chunk = (n + 1023) / 1024;
    int start = tid * chunk;
    int end = min(start + chunk, n);
    int s = 0;
    for (int i = start; i < end; i++) s += g_count[i];
    sums[tid] = s;
    __syncthreads();
    for (int off = 1; off < 1024; off <<= 1) {
        int v = (tid >= off) ? sums[tid - off] : 0;
        __syncthreads();
        sums[tid] += v;
        __syncthreads();
    }
    int excl = (tid == 0) ? 0 : sums[tid - 1];
    for (int i = start; i < end; i++) {
        g_offsets[i] = excl;
        excl += g_count[i];
    }
    if (tid == 1023) g_offsets[n] = sums[1023];
}

__global__ void dinv_kernel(int n) {
    for (int i = blockIdx.x * blockDim.x + threadIdx.x; i < n;
         i += gridDim.x * blockDim.x) {
        g_dinv[i] = rsqrtf((float)(g_count[i] + 1));
    }
}

__global__ void scatter_kernel(const void* __restrict__ edges, int E) {
    for (int i = blockIdx.x * blockDim.x + threadIdx.x; i < E;
         i += gridDim.x * blockDim.x) {
        int s = (int)ld_idx(edges, i);
        int d = (int)ld_idx(edges, (size_t)E + i);
        if (s < 0 || s >= NN || d < 0 || d >= NN) continue;
        int pos = g_offsets[d] + atomicAdd(&g_cursor[d], 1);
        g_csr[pos] = s;
    }
}

// ---------------------------------------------------------------------------
// Tiled SGEMM: C[M,Nc] = concat_k(A1[M,K1], A2[M,K2]) @ B[K1+K2, Nc]
// BM=BN=128, BK=8, 256 threads, 8x8 per thread. Optional bias + ELU epilogue.
__global__ __launch_bounds__(256) void gemm_kernel(
    const float* __restrict__ A1, int K1,
    const float* __restrict__ A2, int K2,
    const float* __restrict__ B,
    const float* __restrict__ bias,
    float* __restrict__ C, int ldc,
    int M, int Nc, int do_elu)
{
    __shared__ __align__(16) float As[8][128];
    __shared__ __align__(16) float Bs[8][128];
    const int tid = threadIdx.x;
    const int m0 = blockIdx.y * 128;
    const int n0 = blockIdx.x * 128;
    const int tx = tid & 15, ty = tid >> 4;

    float acc[8][8];
#pragma unroll
    for (int i = 0; i < 8; i++)
#pragma unroll
        for (int j = 0; j < 8; j++) acc[i][j] = 0.f;

    const int Ktot = K1 + K2;
    const int ar = tid >> 1;           // 0..127  (A row within tile)
    const int akq = (tid & 1) * 4;     // 0 or 4  (A k-quad)
    const int bkr = tid >> 5;          // 0..7    (B k-row)
    const int bnq = (tid & 31) * 4;    // 0..124  (B n-quad)

    for (int k0 = 0; k0 < Ktot; k0 += 8) {
        const float* A;
        int K, kc;
        if (k0 < K1) { A = A1; K = K1; kc = k0; }
        else         { A = A2; K = K2; kc = k0 - K1; }

        int row = m0 + ar;
        float4 av = make_float4(0.f, 0.f, 0.f, 0.f);
        if (row < M)
            av = *(const float4*)(A + (size_t)row * K + kc + akq);
        As[akq + 0][ar] = av.x;
        As[akq + 1][ar] = av.y;
        As[akq + 2][ar] = av.z;
        As[akq + 3][ar] = av.w;

        float4 bv = *(const float4*)(B + (size_t)(k0 + bkr) * Nc + n0 + bnq);
        *(float4*)&Bs[bkr][bnq] = bv;
        __syncthreads();

#pragma unroll
        for (int k = 0; k < 8; k++) {
            float4 a0 = *(const float4*)&As[k][ty * 8];
            float4 a1 = *(const float4*)&As[k][ty * 8 + 4];
            float4 b0 = *(const float4*)&Bs[k][tx * 8];
            float4 b1 = *(const float4*)&Bs[k][tx * 8 + 4];
            float a[8] = {a0.x, a0.y, a0.z, a0.w, a1.x, a1.y, a1.z, a1.w};
            float b[8] = {b0.x, b0.y, b0.z, b0.w, b1.x, b1.y, b1.z, b1.w};
#pragma unroll
            for (int i = 0; i < 8; i++)
#pragma unroll
                for (int j = 0; j < 8; j++)
                    acc[i][j] = fmaf(a[i], b[j], acc[i][j]);
        }
        __syncthreads();
    }

#pragma unroll
    for (int i = 0; i < 8; i++) {
        int row = m0 + ty * 8 + i;
        if (row >= M) continue;
#pragma unroll
        for (int j = 0; j < 8; j++) {
            int col = n0 + tx * 8 + j;
            float v = acc[i][j];
            if (bias) v += bias[col];
            if (do_elu) v = (v > 0.f) ? v : expm1f(v);
            C[(size_t)row * ldc + col] = v;
        }
    }
}

// ---------------------------------------------------------------------------
// Per-dst-node gather aggregation: gc[d] = sum_{s in in(d)} xw[s]*dinv[s]*dinv[d]
//                                          + xw[d]/deg[d] + bg
__global__ __launch_bounds__(256) void agg_kernel(const float* __restrict__ bg) {
    int row = blockIdx.x;
    int t = threadIdx.x;
    int cnt = g_count[row];
    float deg = (float)(cnt + 1);
    float dinv_r = g_dinv[row];
    float acc = g_xw[(size_t)row * GCO + t] * (1.0f / deg);
    int beg = g_offsets[row], end = beg + cnt;
    for (int e = beg; e < end; e++) {
        int s = g_csr[e];
        float w = dinv_r * __ldg(&g_dinv[s]);
        acc += __ldg(&g_xw[(size_t)s * GCO + t]) * w;
    }
    g_gc[(size_t)row * GCO + t] = acc + bg[t];
}

// ---------------------------------------------------------------------------
__global__ void copy_feats_kernel(const float* __restrict__ feats,
                                  float* __restrict__ out, int N) {
    int tot = N * INF;
    for (int i = blockIdx.x * blockDim.x + threadIdx.x; i < tot;
         i += gridDim.x * blockDim.x) {
        int r = i >> 7;
        int c = i & 127;
        out[(size_t)r * (FO + INF) + FO + c] = feats[i];
    }
}

__global__ void copy_tail_kernel(const void* __restrict__ edges,
                                 const void* __restrict__ batch,
                                 float* __restrict__ out, int N, int E,
                                 long long tailMax) {
    size_t base = (size_t)N * (FO + INF);
    long long tot = 2LL * E + N;
    if (tot > tailMax) tot = tailMax;
    for (long long i = blockIdx.x * (long long)blockDim.x + threadIdx.x; i < tot;
         i += (long long)gridDim.x * blockDim.x) {
        long long v = (i < 2LL * E) ? ld_idx(edges, i) : ld_idx(batch, i - 2LL * E);
        out[base + i] = (float)v;
    }
}

// ---------------------------------------------------------------------------
extern "C" void kernel_launch(void* const* d_in, const int* in_sizes, int n_in,
                              void* d_out, int out_size) {
    const float* feats = (const float*)d_in[0];
    const void*  edges = d_in[1];
    const void*  batch = d_in[2];
    const float* W1    = (const float*)d_in[3];
    const float* b1    = (const float*)d_in[4];
    const float* Wg    = (const float*)d_in[5];
    const float* bg    = (const float*)d_in[6];
    const float* Wc    = (const float*)d_in[7];
    const float* bc    = (const float*)d_in[8];
    float* out = (float*)d_out;

    const int N = NN;
    const int E = EE;

    float *p_nf, *p_xw, *p_gc;
    cudaGetSymbolAddress((void**)&p_nf, g_nfeats);
    cudaGetSymbolAddress((void**)&p_xw, g_xw);
    cudaGetSymbolAddress((void**)&p_gc, g_gc);

    // Edge dtype detection (int32 vs int64), then CSR build (by dst) + degrees
    detect_kernel<<<1, 256>>>((const unsigned int*)edges, 4096);
    zero_kernel<<<256, 256>>>(N);
    hist_kernel<<<512, 256>>>(edges, E);
    scan_kernel<<<1, 1024>>>(N);
    dinv_kernel<<<256, 256>>>(N);
    scatter_kernel<<<512, 256>>>(edges, E);

    // GEMM1: nfeats = elu(feats @ W1 + b1)   [N,128]x[128,256]
    dim3 grid1((HID + 127) / 128, (N + 127) / 128);
    gemm_kernel<<<grid1, 256>>>(feats, INF, nullptr, 0, W1, b1,
                                p_nf, HID, N, HID, 1);

    // GEMM2: xw = [nfeats|feats] @ Wg         [N,384]x[384,256] (no bias)
    dim3 grid2((GCO + 127) / 128, (N + 127) / 128);
    gemm_kernel<<<grid2, 256>>>(p_nf, HID, feats, INF, Wg, nullptr,
                                p_xw, GCO, N, GCO, 0);

    // Aggregation -> gc
    agg_kernel<<<N, 256>>>(bg);

    // GEMM3: out[:, :256] = elu([nfeats|gc] @ Wc + bc), row stride 384
    dim3 grid3((FO + 127) / 128, (N + 127) / 128);
    gemm_kernel<<<grid3, 256>>>(p_nf, HID, p_gc, GCO, Wc, bc,
                                out, FO + INF, N, FO, 1);

    // out[:, 256:384] = feats ; tail = edges, batch (as float)
    copy_feats_kernel<<<512, 256>>>(feats, out, N);
    long long tailMax = (long long)out_size - (long long)N * (FO + INF);
    if (tailMax > 0)
        copy_tail_kernel<<<512, 256>>>(edges, batch, out, N, E, tailMax);
}

// round 4
// speedup vs baseline: 2.6767x; 2.6767x over previous
#include <cuda_runtime.h>
#include <math.h>
#include <stdint.h>

#define NN 100000
#define EE 1600000
#define INF 128
#define HID 256
#define GCO 256
#define FO  256

// ---- mma.sync tf32 GEMM tile config ---------------------------------------
#define BM 128
#define BN 128
#define BK 32
#define LDP 36                      // padded row stride (floats): conflict-free
#define TILE_F (128 * LDP)          // floats per (A or B) tile buffer
#define TILE_B (TILE_F * 4)         // 18432 bytes
#define OFF_A0 0
#define OFF_B0 TILE_B
#define OFF_A1 (2 * TILE_B)
#define OFF_B1 (3 * TILE_B)
#define GEMM_SMEM (4 * TILE_B)      // 73728 bytes

__device__ __forceinline__ uint32_t smem_u32(const void* p) {
    uint32_t a;
    asm("{ .reg .u64 t; cvta.to.shared.u64 t, %1; cvt.u32.u64 %0, t; }"
        : "=r"(a) : "l"(p));
    return a;
}

__device__ __forceinline__ uint32_t f2tf32(float f) {
    uint32_t u;
    asm("cvt.rna.tf32.f32 %0, %1;" : "=r"(u) : "f"(f));
    return u;
}

__device__ __forceinline__ void cp16(uint32_t dst, const void* src, int sz) {
    asm volatile("cp.async.cg.shared.global [%0], [%1], 16, %2;"
                 :: "r"(dst), "l"(src), "r"(sz) : "memory");
}

__device__ __forceinline__ void mma_tf32(float* d, const uint32_t* a,
                                         const uint32_t* b) {
    asm volatile(
        "mma.sync.aligned.m16n8k8.row.col.f32.tf32.tf32.f32 "
        "{%0,%1,%2,%3}, {%4,%5,%6,%7}, {%8,%9}, {%0,%1,%2,%3};"
        : "+f"(d[0]), "+f"(d[1]), "+f"(d[2]), "+f"(d[3])
        : "r"(a[0]), "r"(a[1]), "r"(a[2]), "r"(a[3]), "r"(b[0]), "r"(b[1]));
}

// ---------------------------------------------------------------------------
// Scratch (device globals: allocation-free)
__device__ __align__(16) float g_nfeats[(size_t)NN * HID];
__device__ __align__(16) float g_xw[(size_t)NN * GCO];
__device__ __align__(16) float g_gc[(size_t)NN * GCO];
__device__ __align__(16) float g_W1T[HID * INF];
__device__ __align__(16) float g_WgT[GCO * (HID + INF)];
__device__ __align__(16) float g_WcT[FO * (HID + GCO)];
__device__ int   g_count[NN];
__device__ int   g_cursor[NN];
__device__ int   g_offsets[NN + 1];
__device__ float g_dinv[NN];
__device__ int   g_csr[EE];
__device__ int   g_bsum[512];
__device__ int   g_boff[512];
__device__ int   g_is64;

// ---------------------------------------------------------------------------
__global__ void detect_kernel(const unsigned int* __restrict__ ew, int nPairs) {
    __shared__ int nz;
    if (threadIdx.x == 0) nz = 0;
    __syncthreads();
    for (int i = threadIdx.x; i < nPairs; i += blockDim.x)
        if (ew[2 * i + 1] != 0u) { nz = 1; break; }
    __syncthreads();
    if (threadIdx.x == 0) g_is64 = (nz == 0) ? 1 : 0;
}

__device__ __forceinline__ long long ld_idx(const void* p, size_t i) {
    if (g_is64) return ((const long long*)p)[i];
    return (long long)((const int*)p)[i];
}

__global__ void zero_kernel(int n) {
    for (int i = blockIdx.x * blockDim.x + threadIdx.x; i < n;
         i += gridDim.x * blockDim.x) {
        g_count[i] = 0;
        g_cursor[i] = 0;
    }
}

__global__ void hist_kernel(const void* __restrict__ edges, int E) {
    for (int i = blockIdx.x * blockDim.x + threadIdx.x; i < E;
         i += gridDim.x * blockDim.x) {
        int d = (int)ld_idx(edges, (size_t)E + i);
        if (d >= 0 && d < NN) atomicAdd(&g_count[d], 1);
    }
}

// Parallel scan: S1 block sums, S2 scan of block sums, S3 per-block scan.
__global__ void scan1_kernel(int n) {
    __shared__ int sh[256];
    int i = blockIdx.x * 256 + threadIdx.x;
    sh[threadIdx.x] = (i < n) ? g_count[i] : 0;
    __syncthreads();
    for (int off = 128; off > 0; off >>= 1) {
        if (threadIdx.x < off) sh[threadIdx.x] += sh[threadIdx.x + off];
        __syncthreads();
    }
    if (threadIdx.x == 0) g_bsum[blockIdx.x] = sh[0];
}

__global__ void scan2_kernel(int nb, int n) {
    __shared__ int sh[512];
    int t = threadIdx.x;
    int v = (t < nb) ? g_bsum[t] : 0;
    sh[t] = v;
    __syncthreads();
    for (int off = 1; off < 512; off <<= 1) {
        int x = (t >= off) ? sh[t - off] : 0;
        __syncthreads();
        sh[t] += x;
        __syncthreads();
    }
    if (t < nb) g_boff[t] = sh[t] - v;
    if (t == nb - 1) g_offsets[n] = sh[t];
}

__global__ void scan3_kernel(int n) {
    __shared__ int sh[256];
    int b = blockIdx.x, t = threadIdx.x;
    int i = b * 256 + t;
    int v = (i < n) ? g_count[i] : 0;
    sh[t] = v;
    __syncthreads();
    for (int off = 1; off < 256; off <<= 1) {
        int x = (t >= off) ? sh[t - off] : 0;
        __syncthreads();
        sh[t] += x;
        __syncthreads();
    }
    if (i < n) g_offsets[i] = sh[t] - v + g_boff[b];
}

__global__ void dinv_kernel(int n) {
    for (int i = blockIdx.x * blockDim.x + threadIdx.x; i < n;
         i += gridDim.x * blockDim.x)
        g_dinv[i] = rsqrtf((float)(g_count[i] + 1));
}

__global__ void scatter_kernel(const void* __restrict__ edges, int E) {
    for (int i = blockIdx.x * blockDim.x + threadIdx.x; i < E;
         i += gridDim.x * blockDim.x) {
        int s = (int)ld_idx(edges, i);
        int d = (int)ld_idx(edges, (size_t)E + i);
        if (s < 0 || s >= NN || d < 0 || d >= NN) continue;
        int pos = g_offsets[d] + atomicAdd(&g_cursor[d], 1);
        g_csr[pos] = s;
    }
}

// ---------------------------------------------------------------------------
// Transpose weights W[K,256] -> WT[256,K], rounded to tf32.
__global__ void transpose_kernel(const float* __restrict__ W,
                                 float* __restrict__ WT, int K) {
    int tot = K * 256;
    for (int i = blockIdx.x * blockDim.x + threadIdx.x; i < tot;
         i += gridDim.x * blockDim.x) {
        int k = i >> 8, n = i & 255;
        uint32_t u = f2tf32(W[(size_t)k * 256 + n]);
        WT[(size_t)n * K + k] = __uint_as_float(u);
    }
}

// ---------------------------------------------------------------------------
// tf32 mma.sync GEMM: C[M,256] = concat_k(A1[M,K1], A2[M,K2]) @ WT^T
// WT is [256, Ktot] row-major (tf32-rounded). Optional bias + ELU epilogue.
// Grid: (Ntiles=2, Mtiles). 256 threads: 8 warps in 4(M) x 2(N) grid;
// warp tile 32x64 = 2 m-subtiles x 8 n-subtiles of m16n8k8.
__global__ __launch_bounds__(256) void tc_gemm(
    const float* __restrict__ A1, int K1,
    const float* __restrict__ A2, int K2,
    const float* __restrict__ BT,
    const float* __restrict__ bias,
    float* __restrict__ C, int ldc, int M, int do_elu)
{
    extern __shared__ char smem[];
    const uint32_t sb = smem_u32(smem);
    const int tid = threadIdx.x;
    const int wid = tid >> 5, lid = tid & 31;
    const int wm = wid >> 1, wn = wid & 1;
    const int m0 = blockIdx.y * BM;
    const int n0 = blockIdx.x * BN;
    const int Ktot = K1 + K2;
    const int nT = Ktot / BK;

    // per-thread load coords: row = tid>>1 (0..127), half = tid&1 (16 floats)
    const int ldr = tid >> 1;
    const int ldh = (tid & 1) * 16;

    float acc[2][8][4];
#pragma unroll
    for (int i = 0; i < 2; i++)
#pragma unroll
        for (int j = 0; j < 8; j++)
#pragma unroll
            for (int q = 0; q < 4; q++) acc[i][j][q] = 0.f;

    // ---- async load of stage s for k-tile t ----
    auto load_stage = [&](int t) {
        const int s = t & 1;
        const uint32_t aOff = s ? OFF_A1 : OFF_A0;
        const uint32_t bOff = s ? OFF_B1 : OFF_B0;
        const int k0 = t * BK;
        const float* A; int K, kc;
        if (k0 < K1) { A = A1; K = K1; kc = k0; }
        else         { A = A2; K = K2; kc = k0 - K1; }
        const int arow = m0 + ldr;
        const int asz = (arow < M) ? 16 : 0;
        const float* asrc = A + (size_t)arow * K + kc + ldh;
        const float* bsrc = BT + (size_t)(n0 + ldr) * Ktot + k0 + ldh;
        const uint32_t adst = sb + aOff + (ldr * LDP + ldh) * 4;
        const uint32_t bdst = sb + bOff + (ldr * LDP + ldh) * 4;
#pragma unroll
        for (int j = 0; j < 4; j++) {
            cp16(adst + j * 16, asrc + j * 4, asz);
            cp16(bdst + j * 16, bsrc + j * 4, 16);
        }
        asm volatile("cp.async.commit_group;" ::: "memory");
    };

    load_stage(0);

    for (int t = 0; t < nT; t++) {
        if (t + 1 < nT) {
            load_stage(t + 1);
            asm volatile("cp.async.wait_group 1;" ::: "memory");
        } else {
            asm volatile("cp.async.wait_group 0;" ::: "memory");
        }
        __syncthreads();

        const int s = t & 1;
        const float* As = (const float*)(smem + (s ? OFF_A1 : OFF_A0));
        const float* Bs = (const float*)(smem + (s ? OFF_B1 : OFF_B0));
        const uint32_t* Bu = (const uint32_t*)Bs;

        const int g = lid >> 2;       // 0..7
        const int lg = lid & 3;       // 0..3

#pragma unroll
        for (int kk = 0; kk < 4; kk++) {
            const int k8 = kk * 8;
            uint32_t a[2][4];
#pragma unroll
            for (int mt = 0; mt < 2; mt++) {
                const int r0 = wm * 32 + mt * 16 + g;
                a[mt][0] = f2tf32(As[(r0)     * LDP + k8 + lg]);
                a[mt][1] = f2tf32(As[(r0 + 8) * LDP + k8 + lg]);
                a[mt][2] = f2tf32(As[(r0)     * LDP + k8 + lg + 4]);
                a[mt][3] = f2tf32(As[(r0 + 8) * LDP + k8 + lg + 4]);
            }
#pragma unroll
            for (int nt = 0; nt < 8; nt++) {
                const int c0 = wn * 64 + nt * 8 + g;
                uint32_t b[2];
                b[0] = Bu[c0 * LDP + k8 + lg];
                b[1] = Bu[c0 * LDP + k8 + lg + 4];
                mma_tf32(acc[0][nt], a[0], b);
                mma_tf32(acc[1][nt], a[1], b);
            }
        }
        __syncthreads();
    }

    // ---- epilogue: bias + ELU, float2 stores ----
    const int g = lid >> 2;
    const int lg = lid & 3;
#pragma unroll
    for (int mt = 0; mt < 2; mt++) {
        const int r0 = m0 + wm * 32 + mt * 16 + g;
#pragma unroll
        for (int nt = 0; nt < 8; nt++) {
            const int col = n0 + wn * 64 + nt * 8 + lg * 2;
            float b0 = 0.f, b1 = 0.f;
            if (bias) { b0 = __ldg(&bias[col]); b1 = __ldg(&bias[col + 1]); }
            float x0 = acc[mt][nt][0] + b0;
            float x1 = acc[mt][nt][1] + b1;
            float x2 = acc[mt][nt][2] + b0;
            float x3 = acc[mt][nt][3] + b1;
            if (do_elu) {
                x0 = (x0 > 0.f) ? x0 : expm1f(x0);
                x1 = (x1 > 0.f) ? x1 : expm1f(x1);
                x2 = (x2 > 0.f) ? x2 : expm1f(x2);
                x3 = (x3 > 0.f) ? x3 : expm1f(x3);
            }
            if (r0 < M)
                *(float2*)(C + (size_t)r0 * ldc + col) = make_float2(x0, x1);
            if (r0 + 8 < M)
                *(float2*)(C + (size_t)(r0 + 8) * ldc + col) = make_float2(x2, x3);
        }
    }
}

// ---------------------------------------------------------------------------
// Per-dst-node gather aggregation (float4, 64 threads per node).
__global__ __launch_bounds__(64) void agg_kernel(const float* __restrict__ bg) {
    const int row = blockIdx.x;
    const int t = threadIdx.x;
    const float4* xw4 = (const float4*)g_xw;
    float4* gc4 = (float4*)g_gc;
    const int cnt = g_count[row];
    const float inv_deg = 1.0f / (float)(cnt + 1);
    const float dinv_r = g_dinv[row];
    float4 a = xw4[(size_t)row * 64 + t];
    float4 acc = make_float4(a.x * inv_deg, a.y * inv_deg,
                             a.z * inv_deg, a.w * inv_deg);
    const int beg = g_offsets[row], end = beg + cnt;
    for (int e = beg; e < end; e++) {
        int s = g_csr[e];
        float w = dinv_r * __ldg(&g_dinv[s]);
        float4 x = __ldg(&xw4[(size_t)s * 64 + t]);
        acc.x += x.x * w; acc.y += x.y * w;
        acc.z += x.z * w; acc.w += x.w * w;
    }
    float4 b = __ldg(&((const float4*)bg)[t]);
    acc.x += b.x; acc.y += b.y; acc.z += b.z; acc.w += b.w;
    gc4[(size_t)row * 64 + t] = acc;
}

// ---------------------------------------------------------------------------
__global__ void copy_feats_kernel(const float4* __restrict__ feats4,
                                  float4* __restrict__ out4, int N) {
    int tot = N * 32;  // 128 floats = 32 float4 per row
    for (int i = blockIdx.x * blockDim.x + threadIdx.x; i < tot;
         i += gridDim.x * blockDim.x) {
        int r = i >> 5, c = i & 31;
        out4[(size_t)r * 96 + 64 + c] = feats4[i];
    }
}

__global__ void copy_tail_kernel(const void* __restrict__ edges,
                                 const void* __restrict__ batch,
                                 float* __restrict__ out, int N, int E,
                                 long long tailMax) {
    size_t base = (size_t)N * (FO + INF);
    long long tot = 2LL * E + N;
    if (tot > tailMax) tot = tailMax;
    for (long long i = blockIdx.x * (long long)blockDim.x + threadIdx.x; i < tot;
         i += (long long)gridDim.x * blockDim.x) {
        long long v = (i < 2LL * E) ? ld_idx(edges, i) : ld_idx(batch, i - 2LL * E);
        out[base + i] = (float)v;
    }
}

// ---------------------------------------------------------------------------
extern "C" void kernel_launch(void* const* d_in, const int* in_sizes, int n_in,
                              void* d_out, int out_size) {
    const float* feats = (const float*)d_in[0];
    const void*  edges = d_in[1];
    const void*  batch = d_in[2];
    const float* W1    = (const float*)d_in[3];
    const float* b1    = (const float*)d_in[4];
    const float* Wg    = (const float*)d_in[5];
    const float* bg    = (const float*)d_in[6];
    const float* Wc    = (const float*)d_in[7];
    const float* bc    = (const float*)d_in[8];
    float* out = (float*)d_out;

    const int N = NN, E = EE;
    const int nBlk = (N + 255) / 256;  // 391

    float *p_nf, *p_xw, *p_gc, *p_w1t, *p_wgt, *p_wct;
    cudaGetSymbolAddress((void**)&p_nf, g_nfeats);
    cudaGetSymbolAddress((void**)&p_xw, g_xw);
    cudaGetSymbolAddress((void**)&p_gc, g_gc);
    cudaGetSymbolAddress((void**)&p_w1t, g_W1T);
    cudaGetSymbolAddress((void**)&p_wgt, g_WgT);
    cudaGetSymbolAddress((void**)&p_wct, g_WcT);

    static int attr_done = 0;
    if (!attr_done) {
        cudaFuncSetAttribute(tc_gemm, cudaFuncAttributeMaxDynamicSharedMemorySize,
                             GEMM_SMEM);
        attr_done = 1;
    }

    // CSR build (by dst) + degrees
    detect_kernel<<<1, 256>>>((const unsigned int*)edges, 4096);
    zero_kernel<<<256, 256>>>(N);
    hist_kernel<<<512, 256>>>(edges, E);
    scan1_kernel<<<nBlk, 256>>>(N);
    scan2_kernel<<<1, 512>>>(nBlk, N);
    scan3_kernel<<<nBlk, 256>>>(N);
    dinv_kernel<<<256, 256>>>(N);
    scatter_kernel<<<512, 256>>>(edges, E);

    // Weight transposes (tf32-rounded)
    transpose_kernel<<<128, 256>>>(W1, p_w1t, INF);
    transpose_kernel<<<384, 256>>>(Wg, p_wgt, HID + INF);
    transpose_kernel<<<512, 256>>>(Wc, p_wct, HID + GCO);

    const int nMT = (N + BM - 1) / BM;  // 782
    dim3 grid(2, nMT);

    // GEMM1: nfeats = elu(feats @ W1 + b1)
    tc_gemm<<<grid, 256, GEMM_SMEM>>>(feats, INF, nullptr, 0, p_w1t, b1,
                                      p_nf, HID, N, 1);
    // GEMM2: xw = [nfeats|feats] @ Wg (no bias)
    tc_gemm<<<grid, 256, GEMM_SMEM>>>(p_nf, HID, feats, INF, p_wgt, nullptr,
                                      p_xw, GCO, N, 0);
    // Aggregation -> gc (includes bg)
    agg_kernel<<<N, 64>>>(bg);
    // GEMM3: out[:, :256] = elu([nfeats|gc] @ Wc + bc), row stride 384
    tc_gemm<<<grid, 256, GEMM_SMEM>>>(p_nf, HID, p_gc, GCO, p_wct, bc,
                                      out, FO + INF, N, 1);

    // out[:, 256:384] = feats ; tail = edges, batch (as float)
    copy_feats_kernel<<<512, 256>>>((const float4*)feats, (float4*)out, N);
    long long tailMax = (long long)out_size - (long long)N * (FO + INF);
    if (tailMax > 0)
        copy_tail_kernel<<<512, 256>>>(edges, batch, out, N, E, tailMax);
}

// round 5
// speedup vs baseline: 2.7791x; 1.0383x over previous
#include <cuda_runtime.h>
#include <math.h>
#include <stdint.h>

#define NN 100000
#define EE 1600000
#define INF 128
#define HID 256
#define GCO 256
#define FO  256

// ---- mma.sync tf32 GEMM tile config ---------------------------------------
#define BM 128
#define BN 128
#define BK 32
#define LDP 36                      // padded row stride (floats): conflict-free
#define TILE_F (128 * LDP)          // floats per (A or B) tile buffer
#define TILE_B (TILE_F * 4)         // 18432 bytes
#define NSTAGE 3
#define GEMM_SMEM (NSTAGE * 2 * TILE_B)   // 110592 bytes

__device__ __forceinline__ uint32_t smem_u32(const void* p) {
    uint32_t a;
    asm("{ .reg .u64 t; cvta.to.shared.u64 t, %1; cvt.u32.u64 %0, t; }"
        : "=r"(a) : "l"(p));
    return a;
}

__device__ __forceinline__ uint32_t f2tf32(float f) {
    uint32_t u;
    asm("cvt.rna.tf32.f32 %0, %1;" : "=r"(u) : "f"(f));
    return u;
}

__device__ __forceinline__ void cp16(uint32_t dst, const void* src, int sz) {
    asm volatile("cp.async.cg.shared.global [%0], [%1], 16, %2;"
                 :: "r"(dst), "l"(src), "r"(sz) : "memory");
}

__device__ __forceinline__ void mma_tf32(float* d, const uint32_t* a,
                                         const uint32_t* b) {
    asm volatile(
        "mma.sync.aligned.m16n8k8.row.col.f32.tf32.tf32.f32 "
        "{%0,%1,%2,%3}, {%4,%5,%6,%7}, {%8,%9}, {%0,%1,%2,%3};"
        : "+f"(d[0]), "+f"(d[1]), "+f"(d[2]), "+f"(d[3])
        : "r"(a[0]), "r"(a[1]), "r"(a[2]), "r"(a[3]), "r"(b[0]), "r"(b[1]));
}

// ---------------------------------------------------------------------------
// Scratch (device globals: allocation-free)
__device__ __align__(16) float g_nfeats[(size_t)NN * HID];
__device__ __align__(16) float g_xw[(size_t)NN * GCO];
__device__ __align__(16) float g_gc[(size_t)NN * GCO];
__device__ __align__(16) float g_W1T[HID * INF];
__device__ __align__(16) float g_WgT[GCO * (HID + INF)];
__device__ __align__(16) float g_WcT[FO * (HID + GCO)];
__device__ int   g_count[NN];
__device__ int   g_cursor[NN];
__device__ int   g_offsets[NN + 1];
__device__ float g_dinv[NN];
__device__ int   g_csr[EE];
__device__ int   g_bsum[512];
__device__ int   g_boff[512];
__device__ int   g_is64;

// ---------------------------------------------------------------------------
__global__ void detect_kernel(const unsigned int* __restrict__ ew, int nPairs) {
    __shared__ int nz;
    if (threadIdx.x == 0) nz = 0;
    __syncthreads();
    for (int i = threadIdx.x; i < nPairs; i += blockDim.x)
        if (ew[2 * i + 1] != 0u) { nz = 1; break; }
    __syncthreads();
    if (threadIdx.x == 0) g_is64 = (nz == 0) ? 1 : 0;
}

__device__ __forceinline__ long long ld_idx(const void* p, size_t i) {
    if (g_is64) return ((const long long*)p)[i];
    return (long long)((const int*)p)[i];
}

__global__ void zero_kernel(int n) {
    for (int i = blockIdx.x * blockDim.x + threadIdx.x; i < n;
         i += gridDim.x * blockDim.x) {
        g_count[i] = 0;
        g_cursor[i] = 0;
    }
}

__global__ void hist_kernel(const void* __restrict__ edges, int E) {
    for (int i = blockIdx.x * blockDim.x + threadIdx.x; i < E;
         i += gridDim.x * blockDim.x) {
        int d = (int)ld_idx(edges, (size_t)E + i);
        if (d >= 0 && d < NN) atomicAdd(&g_count[d], 1);
    }
}

// Parallel scan: S1 block sums, S2 scan of block sums, S3 per-block scan.
__global__ void scan1_kernel(int n) {
    __shared__ int sh[256];
    int i = blockIdx.x * 256 + threadIdx.x;
    sh[threadIdx.x] = (i < n) ? g_count[i] : 0;
    __syncthreads();
    for (int off = 128; off > 0; off >>= 1) {
        if (threadIdx.x < off) sh[threadIdx.x] += sh[threadIdx.x + off];
        __syncthreads();
    }
    if (threadIdx.x == 0) g_bsum[blockIdx.x] = sh[0];
}

__global__ void scan2_kernel(int nb, int n) {
    __shared__ int sh[512];
    int t = threadIdx.x;
    int v = (t < nb) ? g_bsum[t] : 0;
    sh[t] = v;
    __syncthreads();
    for (int off = 1; off < 512; off <<= 1) {
        int x = (t >= off) ? sh[t - off] : 0;
        __syncthreads();
        sh[t] += x;
        __syncthreads();
    }
    if (t < nb) g_boff[t] = sh[t] - v;
    if (t == nb - 1) g_offsets[n] = sh[t];
}

__global__ void scan3_kernel(int n) {
    __shared__ int sh[256];
    int b = blockIdx.x, t = threadIdx.x;
    int i = b * 256 + t;
    int v = (i < n) ? g_count[i] : 0;
    sh[t] = v;
    __syncthreads();
    for (int off = 1; off < 256; off <<= 1) {
        int x = (t >= off) ? sh[t - off] : 0;
        __syncthreads();
        sh[t] += x;
        __syncthreads();
    }
    if (i < n) g_offsets[i] = sh[t] - v + g_boff[b];
}

__global__ void dinv_kernel(int n) {
    for (int i = blockIdx.x * blockDim.x + threadIdx.x; i < n;
         i += gridDim.x * blockDim.x)
        g_dinv[i] = rsqrtf((float)(g_count[i] + 1));
}

__global__ void scatter_kernel(const void* __restrict__ edges, int E) {
    for (int i = blockIdx.x * blockDim.x + threadIdx.x; i < E;
         i += gridDim.x * blockDim.x) {
        int s = (int)ld_idx(edges, i);
        int d = (int)ld_idx(edges, (size_t)E + i);
        if (s < 0 || s >= NN || d < 0 || d >= NN) continue;
        int pos = g_offsets[d] + atomicAdd(&g_cursor[d], 1);
        g_csr[pos] = s;
    }
}

// ---------------------------------------------------------------------------
// Transpose weights W[K,256] -> WT[256,K], rounded to tf32.
__global__ void transpose_kernel(const float* __restrict__ W,
                                 float* __restrict__ WT, int K) {
    int tot = K * 256;
    for (int i = blockIdx.x * blockDim.x + threadIdx.x; i < tot;
         i += gridDim.x * blockDim.x) {
        int k = i >> 8, n = i & 255;
        uint32_t u = f2tf32(W[(size_t)k * 256 + n]);
        WT[(size_t)n * K + k] = __uint_as_float(u);
    }
}

// ---------------------------------------------------------------------------
// tf32 mma.sync GEMM: C[M,256] = concat_k(A1[M,K1], A2[M,K2]) @ WT^T
// WT is [256, Ktot] row-major (tf32-rounded). A fed as raw fp32 (HW truncates
// to tf32). 3-stage cp.async pipeline. Optional bias + ELU epilogue.
// Grid: (Ntiles=2, Mtiles). 256 threads: 8 warps 4(M)x2(N), warp tile 32x64.
__global__ __launch_bounds__(256) void tc_gemm(
    const float* __restrict__ A1, int K1,
    const float* __restrict__ A2, int K2,
    const float* __restrict__ BT,
    const float* __restrict__ bias,
    float* __restrict__ C, int ldc, int M, int do_elu)
{
    extern __shared__ char smem[];
    const uint32_t sb = smem_u32(smem);
    const int tid = threadIdx.x;
    const int wid = tid >> 5, lid = tid & 31;
    const int wm = wid >> 1, wn = wid & 1;
    const int m0 = blockIdx.y * BM;
    const int n0 = blockIdx.x * BN;
    const int Ktot = K1 + K2;
    const int nT = Ktot / BK;

    // per-thread load coords: row = tid>>1 (0..127), half = tid&1 (16 floats)
    const int ldr = tid >> 1;
    const int ldh = (tid & 1) * 16;

    float acc[2][8][4];
#pragma unroll
    for (int i = 0; i < 2; i++)
#pragma unroll
        for (int j = 0; j < 8; j++)
#pragma unroll
            for (int q = 0; q < 4; q++) acc[i][j][q] = 0.f;

    auto load_stage = [&](int t) {
        const int s = t % NSTAGE;
        const uint32_t aOff = s * 2 * TILE_B;
        const uint32_t bOff = aOff + TILE_B;
        const int k0 = t * BK;
        const float* A; int K, kc;
        if (k0 < K1) { A = A1; K = K1; kc = k0; }
        else         { A = A2; K = K2; kc = k0 - K1; }
        const int arow = m0 + ldr;
        const int asz = (arow < M) ? 16 : 0;
        const float* asrc = A + (size_t)arow * K + kc + ldh;
        const float* bsrc = BT + (size_t)(n0 + ldr) * Ktot + k0 + ldh;
        const uint32_t adst = sb + aOff + (ldr * LDP + ldh) * 4;
        const uint32_t bdst = sb + bOff + (ldr * LDP + ldh) * 4;
#pragma unroll
        for (int j = 0; j < 4; j++) {
            cp16(adst + j * 16, asrc + j * 4, asz);
            cp16(bdst + j * 16, bsrc + j * 4, 16);
        }
        asm volatile("cp.async.commit_group;" ::: "memory");
    };

    load_stage(0);
    if (nT > 1) load_stage(1);

    for (int t = 0; t < nT; t++) {
        if (t + 2 < nT) {
            load_stage(t + 2);
            asm volatile("cp.async.wait_group 2;" ::: "memory");
        } else if (t + 1 < nT) {
            asm volatile("cp.async.wait_group 1;" ::: "memory");
        } else {
            asm volatile("cp.async.wait_group 0;" ::: "memory");
        }
        __syncthreads();

        const int s = t % NSTAGE;
        const uint32_t* Au = (const uint32_t*)(smem + s * 2 * TILE_B);
        const uint32_t* Bu = (const uint32_t*)(smem + s * 2 * TILE_B + TILE_B);

        const int g = lid >> 2;       // 0..7
        const int lg = lid & 3;       // 0..3

#pragma unroll
        for (int kk = 0; kk < 4; kk++) {
            const int k8 = kk * 8;
            uint32_t a[2][4];
#pragma unroll
            for (int mt = 0; mt < 2; mt++) {
                const int r0 = wm * 32 + mt * 16 + g;
                a[mt][0] = Au[(r0)     * LDP + k8 + lg];
                a[mt][1] = Au[(r0 + 8) * LDP + k8 + lg];
                a[mt][2] = Au[(r0)     * LDP + k8 + lg + 4];
                a[mt][3] = Au[(r0 + 8) * LDP + k8 + lg + 4];
            }
#pragma unroll
            for (int nt = 0; nt < 8; nt++) {
                const int c0 = wn * 64 + nt * 8 + g;
                uint32_t b[2];
                b[0] = Bu[c0 * LDP + k8 + lg];
                b[1] = Bu[c0 * LDP + k8 + lg + 4];
                mma_tf32(acc[0][nt], a[0], b);
                mma_tf32(acc[1][nt], a[1], b);
            }
        }
        __syncthreads();
    }

    // ---- epilogue: bias + ELU, float2 stores ----
    const int g = lid >> 2;
    const int lg = lid & 3;
#pragma unroll
    for (int mt = 0; mt < 2; mt++) {
        const int r0 = m0 + wm * 32 + mt * 16 + g;
#pragma unroll
        for (int nt = 0; nt < 8; nt++) {
            const int col = n0 + wn * 64 + nt * 8 + lg * 2;
            float b0 = 0.f, b1 = 0.f;
            if (bias) { b0 = __ldg(&bias[col]); b1 = __ldg(&bias[col + 1]); }
            float x0 = acc[mt][nt][0] + b0;
            float x1 = acc[mt][nt][1] + b1;
            float x2 = acc[mt][nt][2] + b0;
            float x3 = acc[mt][nt][3] + b1;
            if (do_elu) {
                x0 = (x0 > 0.f) ? x0 : expm1f(x0);
                x1 = (x1 > 0.f) ? x1 : expm1f(x1);
                x2 = (x2 > 0.f) ? x2 : expm1f(x2);
                x3 = (x3 > 0.f) ? x3 : expm1f(x3);
            }
            if (r0 < M)
                *(float2*)(C + (size_t)r0 * ldc + col) = make_float2(x0, x1);
            if (r0 + 8 < M)
                *(float2*)(C + (size_t)(r0 + 8) * ldc + col) = make_float2(x2, x3);
        }
    }
}

// ---------------------------------------------------------------------------
// Per-dst-node gather aggregation: 4 nodes per 256-thread block, float4 lanes.
__global__ __launch_bounds__(256) void agg_kernel(const float* __restrict__ bg,
                                                  int N) {
    const int row = blockIdx.x * 4 + (threadIdx.x >> 6);
    const int t = threadIdx.x & 63;
    if (row >= N) return;
    const float4* xw4 = (const float4*)g_xw;
    float4* gc4 = (float4*)g_gc;
    const int cnt = g_count[row];
    const float inv_deg = 1.0f / (float)(cnt + 1);
    const float dinv_r = g_dinv[row];
    float4 a = xw4[(size_t)row * 64 + t];
    float4 acc = make_float4(a.x * inv_deg, a.y * inv_deg,
                             a.z * inv_deg, a.w * inv_deg);
    const int beg = g_offsets[row], end = beg + cnt;
    for (int e = beg; e < end; e++) {
        int s = g_csr[e];
        float w = dinv_r * __ldg(&g_dinv[s]);
        float4 x = __ldg(&xw4[(size_t)s * 64 + t]);
        acc.x += x.x * w; acc.y += x.y * w;
        acc.z += x.z * w; acc.w += x.w * w;
    }
    float4 b = __ldg(&((const float4*)bg)[t]);
    acc.x += b.x; acc.y += b.y; acc.z += b.z; acc.w += b.w;
    gc4[(size_t)row * 64 + t] = acc;
}

// ---------------------------------------------------------------------------
__global__ void copy_feats_kernel(const float4* __restrict__ feats4,
                                  float4* __restrict__ out4, int N) {
    int tot = N * 32;  // 128 floats = 32 float4 per row
    for (int i = blockIdx.x * blockDim.x + threadIdx.x; i < tot;
         i += gridDim.x * blockDim.x) {
        int r = i >> 5, c = i & 31;
        out4[(size_t)r * 96 + 64 + c] = feats4[i];
    }
}

__global__ void copy_tail_kernel(const void* __restrict__ edges,
                                 const void* __restrict__ batch,
                                 float* __restrict__ out, int N, int E,
                                 long long tailMax) {
    size_t base = (size_t)N * (FO + INF);
    long long tot = 2LL * E + N;
    if (tot > tailMax) tot = tailMax;
    for (long long i = blockIdx.x * (long long)blockDim.x + threadIdx.x; i < tot;
         i += (long long)gridDim.x * blockDim.x) {
        long long v = (i < 2LL * E) ? ld_idx(edges, i) : ld_idx(batch, i - 2LL * E);
        out[base + i] = (float)v;
    }
}

// ---------------------------------------------------------------------------
extern "C" void kernel_launch(void* const* d_in, const int* in_sizes, int n_in,
                              void* d_out, int out_size) {
    const float* feats = (const float*)d_in[0];
    const void*  edges = d_in[1];
    const void*  batch = d_in[2];
    const float* W1    = (const float*)d_in[3];
    const float* b1    = (const float*)d_in[4];
    const float* Wg    = (const float*)d_in[5];
    const float* bg    = (const float*)d_in[6];
    const float* Wc    = (const float*)d_in[7];
    const float* bc    = (const float*)d_in[8];
    float* out = (float*)d_out;

    const int N = NN, E = EE;
    const int nBlk = (N + 255) / 256;  // 391

    float *p_nf, *p_xw, *p_gc, *p_w1t, *p_wgt, *p_wct;
    cudaGetSymbolAddress((void**)&p_nf, g_nfeats);
    cudaGetSymbolAddress((void**)&p_xw, g_xw);
    cudaGetSymbolAddress((void**)&p_gc, g_gc);
    cudaGetSymbolAddress((void**)&p_w1t, g_W1T);
    cudaGetSymbolAddress((void**)&p_wgt, g_WgT);
    cudaGetSymbolAddress((void**)&p_wct, g_WcT);

    static cudaStream_t s1 = nullptr;
    static cudaEvent_t evFork = nullptr, evCSR = nullptr, evSide = nullptr;
    if (!s1) {
        cudaFuncSetAttribute(tc_gemm, cudaFuncAttributeMaxDynamicSharedMemorySize,
                             GEMM_SMEM);
        cudaStreamCreateWithFlags(&s1, cudaStreamNonBlocking);
        cudaEventCreateWithFlags(&evFork, cudaEventDisableTiming);
        cudaEventCreateWithFlags(&evCSR, cudaEventDisableTiming);
        cudaEventCreateWithFlags(&evSide, cudaEventDisableTiming);
    }

    // ---- fork side stream ----
    cudaEventRecord(evFork, 0);
    cudaStreamWaitEvent(s1, evFork, 0);

    // side stream: CSR build (by dst) + degrees, then output copies
    detect_kernel<<<1, 256, 0, s1>>>((const unsigned int*)edges, 4096);
    zero_kernel<<<256, 256, 0, s1>>>(N);
    hist_kernel<<<512, 256, 0, s1>>>(edges, E);
    scan1_kernel<<<nBlk, 256, 0, s1>>>(N);
    scan2_kernel<<<1, 512, 0, s1>>>(nBlk, N);
    scan3_kernel<<<nBlk, 256, 0, s1>>>(N);
    dinv_kernel<<<256, 256, 0, s1>>>(N);
    scatter_kernel<<<512, 256, 0, s1>>>(edges, E);
    cudaEventRecord(evCSR, s1);
    copy_feats_kernel<<<512, 256, 0, s1>>>((const float4*)feats, (float4*)out, N);
    long long tailMax = (long long)out_size - (long long)N * (FO + INF);
    if (tailMax > 0)
        copy_tail_kernel<<<512, 256, 0, s1>>>(edges, batch, out, N, E, tailMax);
    cudaEventRecord(evSide, s1);

    // main stream: weight transposes then GEMMs
    transpose_kernel<<<128, 256>>>(W1, p_w1t, INF);
    transpose_kernel<<<384, 256>>>(Wg, p_wgt, HID + INF);
    transpose_kernel<<<512, 256>>>(Wc, p_wct, HID + GCO);

    const int nMT = (N + BM - 1) / BM;  // 782
    dim3 grid(2, nMT);

    // GEMM1: nfeats = elu(feats @ W1 + b1)
    tc_gemm<<<grid, 256, GEMM_SMEM>>>(feats, INF, nullptr, 0, p_w1t, b1,
                                      p_nf, HID, N, 1);
    // GEMM2: xw = [nfeats|feats] @ Wg (no bias)
    tc_gemm<<<grid, 256, GEMM_SMEM>>>(p_nf, HID, feats, INF, p_wgt, nullptr,
                                      p_xw, GCO, N, 0);

    // join: aggregation needs CSR + xw
    cudaStreamWaitEvent(0, evCSR, 0);
    agg_kernel<<<(N + 3) / 4, 256>>>(bg, N);

    // GEMM3: out[:, :256] = elu([nfeats|gc] @ Wc + bc), row stride 384
    tc_gemm<<<grid, 256, GEMM_SMEM>>>(p_nf, HID, p_gc, GCO, p_wct, bc,
                                      out, FO + INF, N, 1);

    // join side-stream copies before returning
    cudaStreamWaitEvent(0, evSide, 0);
}